// round 1
// baseline (speedup 1.0000x reference)
#include <cuda_runtime.h>
#include <math.h>

// Problem constants
constexpr int cB   = 32;
constexpr int cN   = 256;
constexpr int cCIN = 64;
constexpr int cCH  = 128;   // C_H == C_OUT
constexpr int cR   = 5;
constexpr int cJR  = cN * cR;       // 1280
constexpr int cXD  = 1024;
constexpr float cNEG = -9e15f;

constexpr int MASK_WORDS_PER_ROW = cJR / 32;  // 40
constexpr int ATTN_TILE_I = 16;
constexpr int ATTN_SMEM = (ATTN_TILE_I * cJR + cJR + ATTN_TILE_I * cR + ATTN_TILE_I
                           + ATTN_TILE_I * MASK_WORDS_PER_ROW) * 4;  // 89,984 B

// ---------------- device scratch (no cudaMalloc allowed) ----------------
__device__ float    g_h[cB * cN * cR * cCH];            // (b,n,r,c) == row-major (8192, 640)
__device__ float    g_atoms[cB * cN * cCH];             // layer activations (b,n,c)
__device__ float    g_src[cB * cN * cR];
__device__ float    g_dst[cB * cN * cR];
__device__ unsigned g_mask[cB * cN * MASK_WORDS_PER_ROW];
__device__ float    g_pool[cB * 2 * cCH];               // [mean(128) | max(128)] per batch

__device__ __forceinline__ float leaky(float v) { return v >= 0.f ? v : 0.2f * v; }

// ---------------- 1) pack bond mask into bits ----------------
__global__ __launch_bounds__(256) void pack_mask_kernel(const int* __restrict__ bonds) {
    int w = blockIdx.x * blockDim.x + threadIdx.x;     // word index
    if (w >= cB * cN * MASK_WORDS_PER_ROW) return;
    const int4* p = reinterpret_cast<const int4*>(bonds) + w * 8;  // 32 ints
    unsigned m = 0;
#pragma unroll
    for (int q = 0; q < 8; q++) {
        int4 v = p[q];
        m |= (v.x == 1 ? 1u : 0u) << (q * 4 + 0);
        m |= (v.y == 1 ? 1u : 0u) << (q * 4 + 1);
        m |= (v.z == 1 ? 1u : 0u) << (q * 4 + 2);
        m |= (v.w == 1 ? 1u : 0u) << (q * 4 + 3);
    }
    g_mask[w] = m;
}

// ---------------- 2) h = A @ W + bias   (M=8192, N=640, K=64/128) ----------------
template <int K>
__global__ __launch_bounds__(256) void gemm_bias_kernel(const float* __restrict__ A,
                                                        const float* __restrict__ W,
                                                        const float* __restrict__ bias) {
    __shared__ float As[16][64];   // [k][m]
    __shared__ float Bs[16][64];   // [k][n]
    const int t  = threadIdx.x;
    const int tx = t & 15, ty = t >> 4;
    const int bm = blockIdx.y * 64, bn = blockIdx.x * 64;

    float acc[4][4];
#pragma unroll
    for (int i = 0; i < 4; i++)
#pragma unroll
        for (int j = 0; j < 4; j++) acc[i][j] = 0.f;

    const int arow = t >> 2, akq = t & 3;
    const int bkr = t >> 4, bn4 = t & 15;

    for (int bk = 0; bk < K; bk += 16) {
        float4 av = *reinterpret_cast<const float4*>(&A[(bm + arow) * K + bk + akq * 4]);
        As[akq * 4 + 0][arow] = av.x;
        As[akq * 4 + 1][arow] = av.y;
        As[akq * 4 + 2][arow] = av.z;
        As[akq * 4 + 3][arow] = av.w;
        *reinterpret_cast<float4*>(&Bs[bkr][bn4 * 4]) =
            *reinterpret_cast<const float4*>(&W[(bk + bkr) * 640 + bn + bn4 * 4]);
        __syncthreads();
#pragma unroll
        for (int k = 0; k < 16; k++) {
            float4 a  = *reinterpret_cast<float4*>(&As[k][ty * 4]);
            float4 bv = *reinterpret_cast<float4*>(&Bs[k][tx * 4]);
            acc[0][0] += a.x * bv.x; acc[0][1] += a.x * bv.y; acc[0][2] += a.x * bv.z; acc[0][3] += a.x * bv.w;
            acc[1][0] += a.y * bv.x; acc[1][1] += a.y * bv.y; acc[1][2] += a.y * bv.z; acc[1][3] += a.y * bv.w;
            acc[2][0] += a.z * bv.x; acc[2][1] += a.z * bv.y; acc[2][2] += a.z * bv.z; acc[2][3] += a.z * bv.w;
            acc[3][0] += a.w * bv.x; acc[3][1] += a.w * bv.y; acc[3][2] += a.w * bv.z; acc[3][3] += a.w * bv.w;
        }
        __syncthreads();
    }
    float4 bb = *reinterpret_cast<const float4*>(&bias[bn + tx * 4]);
#pragma unroll
    for (int i = 0; i < 4; i++) {
        float4 o;
        o.x = acc[i][0] + bb.x; o.y = acc[i][1] + bb.y;
        o.z = acc[i][2] + bb.z; o.w = acc[i][3] + bb.w;
        *reinterpret_cast<float4*>(&g_h[(bm + ty * 4 + i) * 640 + bn + tx * 4]) = o;
    }
}

// ---------------- 3) src/dst projections: (b,n,r) dots over c ----------------
__global__ __launch_bounds__(160) void src_dst_kernel(const float* __restrict__ a) {
    const int bn   = blockIdx.x;           // 0..8191
    const int r    = threadIdx.x >> 5;     // warp = relation
    const int lane = threadIdx.x & 31;
    const float* hrow = &g_h[(bn * cR + r) * cCH];
    float4 hv = *reinterpret_cast<const float4*>(&hrow[lane * 4]);
    float4 as = *reinterpret_cast<const float4*>(&a[r * (2 * cCH) + lane * 4]);
    float4 ad = *reinterpret_cast<const float4*>(&a[r * (2 * cCH) + cCH + lane * 4]);
    float s = hv.x * as.x + hv.y * as.y + hv.z * as.z + hv.w * as.w;
    float d = hv.x * ad.x + hv.y * ad.y + hv.z * ad.z + hv.w * ad.w;
#pragma unroll
    for (int o = 16; o; o >>= 1) {
        s += __shfl_xor_sync(0xffffffffu, s, o);
        d += __shfl_xor_sync(0xffffffffu, d, o);
    }
    if (lane == 0) {
        g_src[bn * cR + r] = s;
        g_dst[bn * cR + r] = d;
    }
}

// ---------------- 4) fused masked softmax + aggregation ----------------
// Block: (b, i-tile of 16 rows), 256 threads.
template <bool LEAKY_OUT>
__global__ __launch_bounds__(256) void attn_kernel() {
    extern __shared__ float sm[];
    float*    s_p    = sm;                              // 16*1280 (unnormalized exp)
    float*    s_dst  = s_p + ATTN_TILE_I * cJR;         // 1280
    float*    s_src  = s_dst + cJR;                     // 80
    float*    s_inv  = s_src + ATTN_TILE_I * cR;        // 16
    unsigned* s_mask = reinterpret_cast<unsigned*>(s_inv + ATTN_TILE_I); // 640 words

    const int b  = blockIdx.x >> 4;
    const int i0 = (blockIdx.x & 15) * ATTN_TILE_I;
    const int t  = threadIdx.x;

    for (int idx = t; idx < cJR; idx += 256) s_dst[idx] = g_dst[b * cJR + idx];
    if (t < ATTN_TILE_I * cR) s_src[t] = g_src[(b * cN + i0) * cR + t];
    for (int idx = t; idx < ATTN_TILE_I * MASK_WORDS_PER_ROW; idx += 256)
        s_mask[idx] = g_mask[(b * cN + i0) * MASK_WORDS_PER_ROW + idx];
    __syncthreads();

    // ---- phase 1: masked leaky logits -> max -> exp -> sum (16 threads / row)
    {
        const int row = t >> 4, l16 = t & 15;
        float* prow = s_p + row * cJR;
        const float* srcr = s_src + row * cR;
        const unsigned* mrow = s_mask + row * MASK_WORDS_PER_ROW;

        float mx = cNEG;
        for (int e = l16; e < cJR; e += 16) {
            int r = e % 5;
            float v = leaky(srcr[r] + s_dst[e]);
            unsigned bit = (mrow[e >> 5] >> (e & 31)) & 1u;
            v = bit ? v : cNEG;
            prow[e] = v;
            mx = fmaxf(mx, v);
        }
#pragma unroll
        for (int o = 8; o; o >>= 1) mx = fmaxf(mx, __shfl_xor_sync(0xffffffffu, mx, o));

        float sum = 0.f;
        for (int e = l16; e < cJR; e += 16) {
            float ev = __expf(prow[e] - mx);
            prow[e] = ev;
            sum += ev;
        }
#pragma unroll
        for (int o = 8; o; o >>= 1) sum += __shfl_xor_sync(0xffffffffu, sum, o);
        if (l16 == 0) s_inv[row] = 1.f / sum;
    }
    __syncthreads();

    // ---- phase 2: out[16][128] = P[16][1280] @ H[1280][128]
    // thread = (c4 = t&31 -> 4 cols, rg = t>>5 -> 2 rows). 8 FMA per 11 instrs.
    {
        const int c4 = t & 31;
        const int rg = t >> 5;
        const int r0 = rg * 2, r1 = rg * 2 + 1;
        const float4* h4 = reinterpret_cast<const float4*>(&g_h[(size_t)b * cJR * cCH]) + c4;
        const float* p0 = s_p + r0 * cJR;
        const float* p1 = s_p + r1 * cJR;
        float4 acc0 = {0.f, 0.f, 0.f, 0.f};
        float4 acc1 = {0.f, 0.f, 0.f, 0.f};
#pragma unroll 4
        for (int jr = 0; jr < cJR; jr++) {
            float4 hv = h4[jr * 32];
            float a0 = p0[jr], a1 = p1[jr];
            acc0.x += a0 * hv.x; acc0.y += a0 * hv.y; acc0.z += a0 * hv.z; acc0.w += a0 * hv.w;
            acc1.x += a1 * hv.x; acc1.y += a1 * hv.y; acc1.z += a1 * hv.z; acc1.w += a1 * hv.w;
        }
        float inv0 = s_inv[r0], inv1 = s_inv[r1];
        acc0.x *= inv0; acc0.y *= inv0; acc0.z *= inv0; acc0.w *= inv0;
        acc1.x *= inv1; acc1.y *= inv1; acc1.z *= inv1; acc1.w *= inv1;
        if (LEAKY_OUT) {
            acc0.x = leaky(acc0.x); acc0.y = leaky(acc0.y); acc0.z = leaky(acc0.z); acc0.w = leaky(acc0.w);
            acc1.x = leaky(acc1.x); acc1.y = leaky(acc1.y); acc1.z = leaky(acc1.z); acc1.w = leaky(acc1.w);
        }
        *reinterpret_cast<float4*>(&g_atoms[(b * cN + i0 + r0) * cCH + c4 * 4]) = acc0;
        *reinterpret_cast<float4*>(&g_atoms[(b * cN + i0 + r1) * cCH + c4 * 4]) = acc1;
    }
}

// ---------------- 5) mean/max pooling over nodes ----------------
__global__ __launch_bounds__(512) void pool_kernel() {
    __shared__ float s_sum[4][cCH];
    __shared__ float s_max[4][cCH];
    const int b  = blockIdx.x;
    const int c  = threadIdx.x & 127;
    const int ch = threadIdx.x >> 7;   // 0..3, 64 nodes each
    float sum = 0.f, mx = -3.4e38f;
    for (int n = ch * 64; n < ch * 64 + 64; n++) {
        float v = g_atoms[(b * cN + n) * cCH + c];
        sum += v;
        mx = fmaxf(mx, v);
    }
    s_sum[ch][c] = sum;
    s_max[ch][c] = mx;
    __syncthreads();
    if (ch == 0) {
        sum = (s_sum[0][c] + s_sum[1][c]) + (s_sum[2][c] + s_sum[3][c]);
        mx = fmaxf(fmaxf(s_max[0][c], s_max[1][c]), fmaxf(s_max[2][c], s_max[3][c]));
        g_pool[b * 256 + c] = sum * (1.f / 256.f);
        g_pool[b * 256 + cCH + c] = mx;
    }
}

// ---------------- 6) final MLP (block per batch) ----------------
__global__ __launch_bounds__(256) void mlp_kernel(const float* __restrict__ x,
                                                  const float* __restrict__ We1, const float* __restrict__ be1,
                                                  const float* __restrict__ We2, const float* __restrict__ be2,
                                                  const float* __restrict__ We3, const float* __restrict__ be3,
                                                  float* __restrict__ out) {
    __shared__ float s_z[cXD + 256];
    __shared__ float s_h1[256];
    __shared__ float s_h2[32];
    const int b = blockIdx.x, t = threadIdx.x;
    for (int i = t; i < cXD; i += 256) s_z[i] = x[b * cXD + i];
    s_z[cXD + t] = g_pool[b * 256 + t];
    __syncthreads();
    {
        float a0 = 0.f, a1 = 0.f, a2 = 0.f, a3 = 0.f;
#pragma unroll 2
        for (int k = 0; k < cXD + 256; k += 4) {
            a0 += s_z[k + 0] * We1[(k + 0) * 256 + t];
            a1 += s_z[k + 1] * We1[(k + 1) * 256 + t];
            a2 += s_z[k + 2] * We1[(k + 2) * 256 + t];
            a3 += s_z[k + 3] * We1[(k + 3) * 256 + t];
        }
        float v = (a0 + a1) + (a2 + a3) + be1[t];
        s_h1[t] = leaky(v);
    }
    __syncthreads();
    if (t < 32) {
        float c0 = 0.f, c1 = 0.f, c2 = 0.f, c3 = 0.f;
        for (int k = 0; k < 256; k += 4) {
            c0 += s_h1[k + 0] * We2[(k + 0) * 32 + t];
            c1 += s_h1[k + 1] * We2[(k + 1) * 32 + t];
            c2 += s_h1[k + 2] * We2[(k + 2) * 32 + t];
            c3 += s_h1[k + 3] * We2[(k + 3) * 32 + t];
        }
        float u = (c0 + c1) + (c2 + c3) + be2[t];
        s_h2[t] = leaky(u);
    }
    __syncthreads();
    if (t < 32) {
        float p = s_h2[t] * We3[t];
#pragma unroll
        for (int o = 16; o; o >>= 1) p += __shfl_xor_sync(0xffffffffu, p, o);
        if (t == 0) out[b] = p + be3[0];
    }
}

// ---------------- launch ----------------
extern "C" void kernel_launch(void* const* d_in, const int* in_sizes, int n_in,
                              void* d_out, int out_size) {
    const float* x       = (const float*)d_in[0];
    const float* y_atoms = (const float*)d_in[1];
    const int*   y_bonds = (const int*)d_in[2];
    const float* W1 = (const float*)d_in[3];
    const float* b1 = (const float*)d_in[4];
    const float* a1 = (const float*)d_in[5];
    const float* W2 = (const float*)d_in[6];
    const float* b2 = (const float*)d_in[7];
    const float* a2 = (const float*)d_in[8];
    const float* W3 = (const float*)d_in[9];
    const float* b3 = (const float*)d_in[10];
    const float* a3 = (const float*)d_in[11];
    const float* We1 = (const float*)d_in[12];
    const float* be1 = (const float*)d_in[13];
    const float* We2 = (const float*)d_in[14];
    const float* be2 = (const float*)d_in[15];
    const float* We3 = (const float*)d_in[16];
    const float* be3 = (const float*)d_in[17];
    float* out = (float*)d_out;

    cudaFuncSetAttribute((const void*)attn_kernel<true>,
                         cudaFuncAttributeMaxDynamicSharedMemorySize, ATTN_SMEM);
    cudaFuncSetAttribute((const void*)attn_kernel<false>,
                         cudaFuncAttributeMaxDynamicSharedMemorySize, ATTN_SMEM);

    float* atoms_ptr = nullptr;
    cudaGetSymbolAddress((void**)&atoms_ptr, g_atoms);

    const dim3 gemm_grid(10, 128);

    pack_mask_kernel<<<(cB * cN * MASK_WORDS_PER_ROW + 255) / 256, 256>>>(y_bonds);

    // layer 1
    gemm_bias_kernel<cCIN><<<gemm_grid, 256>>>(y_atoms, W1, b1);
    src_dst_kernel<<<cB * cN, 160>>>(a1);
    attn_kernel<true><<<cB * 16, 256, ATTN_SMEM>>>();
    // layer 2
    gemm_bias_kernel<cCH><<<gemm_grid, 256>>>(atoms_ptr, W2, b2);
    src_dst_kernel<<<cB * cN, 160>>>(a2);
    attn_kernel<true><<<cB * 16, 256, ATTN_SMEM>>>();
    // layer 3
    gemm_bias_kernel<cCH><<<gemm_grid, 256>>>(atoms_ptr, W3, b3);
    src_dst_kernel<<<cB * cN, 160>>>(a3);
    attn_kernel<false><<<cB * 16, 256, ATTN_SMEM>>>();

    pool_kernel<<<cB, 512>>>();
    mlp_kernel<<<cB, 256>>>(x, We1, be1, We2, be2, We3, be3, out);
}

// round 3
// speedup vs baseline: 1.1869x; 1.1869x over previous
#include <cuda_runtime.h>
#include <cstdint>
#include <math.h>

// Problem constants
constexpr int cB   = 32;
constexpr int cN   = 256;
constexpr int cCIN = 64;
constexpr int cCH  = 128;   // C_H == C_OUT
constexpr int cR   = 5;
constexpr int cJR  = cN * cR;       // 1280
constexpr int cXD  = 1024;
constexpr float cNEG = -9e15f;

constexpr int MASK_WORDS_PER_ROW = cJR / 32;  // 40
constexpr int ATTN_TILE_I = 16;
constexpr int TILE_JR = 16;                    // H rows per smem stage
constexpr int N_JR_TILES = cJR / TILE_JR;      // 80
// smem floats: s_p 20480 + s_dst 1280 + s_src 80 + s_inv 16 + s_mask 640 + s_h 2*16*128
constexpr int ATTN_SMEM = (ATTN_TILE_I * cJR + cJR + ATTN_TILE_I * cR + ATTN_TILE_I
                           + ATTN_TILE_I * MASK_WORDS_PER_ROW
                           + 2 * TILE_JR * cCH) * 4;   // 106,368 B

// ---------------- device scratch (no cudaMalloc allowed) ----------------
__device__ float    g_h[cB * cN * cR * cCH];            // (b,n,r,c) == row-major (8192, 640)
__device__ float    g_atoms[cB * cN * cCH];             // layer activations (b,n,c)
__device__ float    g_src[cB * cN * cR];
__device__ float    g_dst[cB * cN * cR];
__device__ unsigned g_mask[cB * cN * MASK_WORDS_PER_ROW];
__device__ float    g_pool[cB * 2 * cCH];               // [mean(128) | max(128)] per batch

__device__ __forceinline__ float leaky(float v) { return v >= 0.f ? v : 0.2f * v; }

__device__ __forceinline__ void cp_async16(unsigned int smem_dst, const void* gsrc) {
    asm volatile("cp.async.cg.shared.global [%0], [%1], 16;\n" :: "r"(smem_dst), "l"(gsrc));
}
__device__ __forceinline__ void cp_commit() {
    asm volatile("cp.async.commit_group;\n");
}
template <int N>
__device__ __forceinline__ void cp_wait() {
    asm volatile("cp.async.wait_group %0;\n" :: "n"(N));
}

// ---------------- 1) pack bond mask into bits ----------------
__global__ __launch_bounds__(256) void pack_mask_kernel(const int* __restrict__ bonds) {
    int w = blockIdx.x * blockDim.x + threadIdx.x;     // word index
    if (w >= cB * cN * MASK_WORDS_PER_ROW) return;
    const int4* p = reinterpret_cast<const int4*>(bonds) + w * 8;  // 32 ints
    unsigned m = 0;
#pragma unroll
    for (int q = 0; q < 8; q++) {
        int4 v = p[q];
        m |= (v.x == 1 ? 1u : 0u) << (q * 4 + 0);
        m |= (v.y == 1 ? 1u : 0u) << (q * 4 + 1);
        m |= (v.z == 1 ? 1u : 0u) << (q * 4 + 2);
        m |= (v.w == 1 ? 1u : 0u) << (q * 4 + 3);
    }
    g_mask[w] = m;
}

// ---------------- 2) h = A @ W + bias   (M=8192, N=640, K=64/128) ----------------
template <int K>
__global__ __launch_bounds__(256) void gemm_bias_kernel(const float* __restrict__ A,
                                                        const float* __restrict__ W,
                                                        const float* __restrict__ bias) {
    __shared__ float As[16][64];   // [k][m]
    __shared__ float Bs[16][64];   // [k][n]
    const int t  = threadIdx.x;
    const int tx = t & 15, ty = t >> 4;
    const int bm = blockIdx.y * 64, bn = blockIdx.x * 64;

    float acc[4][4];
#pragma unroll
    for (int i = 0; i < 4; i++)
#pragma unroll
        for (int j = 0; j < 4; j++) acc[i][j] = 0.f;

    const int arow = t >> 2, akq = t & 3;
    const int bkr = t >> 4, bn4 = t & 15;

    for (int bk = 0; bk < K; bk += 16) {
        float4 av = *reinterpret_cast<const float4*>(&A[(bm + arow) * K + bk + akq * 4]);
        As[akq * 4 + 0][arow] = av.x;
        As[akq * 4 + 1][arow] = av.y;
        As[akq * 4 + 2][arow] = av.z;
        As[akq * 4 + 3][arow] = av.w;
        *reinterpret_cast<float4*>(&Bs[bkr][bn4 * 4]) =
            *reinterpret_cast<const float4*>(&W[(bk + bkr) * 640 + bn + bn4 * 4]);
        __syncthreads();
#pragma unroll
        for (int k = 0; k < 16; k++) {
            float4 a  = *reinterpret_cast<float4*>(&As[k][ty * 4]);
            float4 bv = *reinterpret_cast<float4*>(&Bs[k][tx * 4]);
            acc[0][0] += a.x * bv.x; acc[0][1] += a.x * bv.y; acc[0][2] += a.x * bv.z; acc[0][3] += a.x * bv.w;
            acc[1][0] += a.y * bv.x; acc[1][1] += a.y * bv.y; acc[1][2] += a.y * bv.z; acc[1][3] += a.y * bv.w;
            acc[2][0] += a.z * bv.x; acc[2][1] += a.z * bv.y; acc[2][2] += a.z * bv.z; acc[2][3] += a.z * bv.w;
            acc[3][0] += a.w * bv.x; acc[3][1] += a.w * bv.y; acc[3][2] += a.w * bv.z; acc[3][3] += a.w * bv.w;
        }
        __syncthreads();
    }
    float4 bb = *reinterpret_cast<const float4*>(&bias[bn + tx * 4]);
#pragma unroll
    for (int i = 0; i < 4; i++) {
        float4 o;
        o.x = acc[i][0] + bb.x; o.y = acc[i][1] + bb.y;
        o.z = acc[i][2] + bb.z; o.w = acc[i][3] + bb.w;
        *reinterpret_cast<float4*>(&g_h[(bm + ty * 4 + i) * 640 + bn + tx * 4]) = o;
    }
}

// ---------------- 3) src/dst projections: (b,n,r) dots over c ----------------
__global__ __launch_bounds__(160) void src_dst_kernel(const float* __restrict__ a) {
    const int bn   = blockIdx.x;           // 0..8191
    const int r    = threadIdx.x >> 5;     // warp = relation
    const int lane = threadIdx.x & 31;
    const float* hrow = &g_h[(bn * cR + r) * cCH];
    float4 hv = *reinterpret_cast<const float4*>(&hrow[lane * 4]);
    float4 as = *reinterpret_cast<const float4*>(&a[r * (2 * cCH) + lane * 4]);
    float4 ad = *reinterpret_cast<const float4*>(&a[r * (2 * cCH) + cCH + lane * 4]);
    float s = hv.x * as.x + hv.y * as.y + hv.z * as.z + hv.w * as.w;
    float d = hv.x * ad.x + hv.y * ad.y + hv.z * ad.z + hv.w * ad.w;
#pragma unroll
    for (int o = 16; o; o >>= 1) {
        s += __shfl_xor_sync(0xffffffffu, s, o);
        d += __shfl_xor_sync(0xffffffffu, d, o);
    }
    if (lane == 0) {
        g_src[bn * cR + r] = s;
        g_dst[bn * cR + r] = d;
    }
}

// ---------------- 4) fused masked softmax + aggregation ----------------
// Block: (b, i-tile of 16 rows), 256 threads.
// Phase 2 streams H through a cp.async double-buffered smem stage and computes
// a 4-row x 2-col register tile per thread (FFMA-throughput-bound).
template <bool LEAKY_OUT>
__global__ __launch_bounds__(256) void attn_kernel() {
    extern __shared__ float sm[];
    float*    s_p    = sm;                              // 16*1280 (unnormalized exp)
    float*    s_dst  = s_p + ATTN_TILE_I * cJR;         // 1280
    float*    s_src  = s_dst + cJR;                     // 80
    float*    s_inv  = s_src + ATTN_TILE_I * cR;        // 16
    unsigned* s_mask = reinterpret_cast<unsigned*>(s_inv + ATTN_TILE_I); // 640 words
    float*    s_h    = reinterpret_cast<float*>(s_mask + ATTN_TILE_I * MASK_WORDS_PER_ROW);
                                                        // 2 * 16 * 128 (16B aligned)

    const int b  = blockIdx.x >> 4;
    const int i0 = (blockIdx.x & 15) * ATTN_TILE_I;
    const int t  = threadIdx.x;

    const float* hbase = &g_h[(size_t)b * cJR * cCH];
    const unsigned int s_h_addr = (unsigned int)__cvta_generic_to_shared(s_h);

    // issue the first two H tiles immediately (latency hidden under phase 1)
    {
#pragma unroll
        for (int tile = 0; tile < 2; tile++) {
            const float* src = hbase + tile * TILE_JR * cCH;
            unsigned int dst = s_h_addr + tile * (TILE_JR * cCH * 4);
#pragma unroll
            for (int q = 0; q < 2; q++) {
                int idx = t + 256 * q;
                int r = idx >> 5, c4 = idx & 31;
                cp_async16(dst + (r * cCH + c4 * 4) * 4, src + r * cCH + c4 * 4);
            }
            cp_commit();
        }
    }

    for (int idx = t; idx < cJR; idx += 256) s_dst[idx] = g_dst[b * cJR + idx];
    if (t < ATTN_TILE_I * cR) s_src[t] = g_src[(b * cN + i0) * cR + t];
    for (int idx = t; idx < ATTN_TILE_I * MASK_WORDS_PER_ROW; idx += 256)
        s_mask[idx] = g_mask[(b * cN + i0) * MASK_WORDS_PER_ROW + idx];
    __syncthreads();

    // ---- phase 1: masked leaky logits -> max -> exp -> sum (16 threads / row)
    {
        const int row = t >> 4, l16 = t & 15;
        float* prow = s_p + row * cJR;
        const float* srcr = s_src + row * cR;
        const unsigned* mrow = s_mask + row * MASK_WORDS_PER_ROW;

        float mx = cNEG;
        for (int e = l16; e < cJR; e += 16) {
            int r = e % 5;
            float v = leaky(srcr[r] + s_dst[e]);
            unsigned bit = (mrow[e >> 5] >> (e & 31)) & 1u;
            v = bit ? v : cNEG;
            prow[e] = v;
            mx = fmaxf(mx, v);
        }
#pragma unroll
        for (int o = 8; o; o >>= 1) mx = fmaxf(mx, __shfl_xor_sync(0xffffffffu, mx, o));

        float sum = 0.f;
        for (int e = l16; e < cJR; e += 16) {
            float ev = __expf(prow[e] - mx);
            prow[e] = ev;
            sum += ev;
        }
#pragma unroll
        for (int o = 8; o; o >>= 1) sum += __shfl_xor_sync(0xffffffffu, sum, o);
        if (l16 == 0) s_inv[row] = 1.f / sum;
    }
    __syncthreads();

    // ---- phase 2: out[16][128] = P[16][1280] @ H[1280][128], H staged via cp.async
    {
        const int c2 = t & 63;                // column pair -> cols c2*2, c2*2+1
        const int rg = t >> 6;                // 0..3 -> rows rg*4 .. rg*4+3
        const float* p0 = s_p + (rg * 4 + 0) * cJR;
        const float* p1 = s_p + (rg * 4 + 1) * cJR;
        const float* p2 = s_p + (rg * 4 + 2) * cJR;
        const float* p3 = s_p + (rg * 4 + 3) * cJR;

        float2 acc0 = {0.f, 0.f}, acc1 = {0.f, 0.f}, acc2 = {0.f, 0.f}, acc3 = {0.f, 0.f};

        for (int tile = 0; tile < N_JR_TILES; tile++) {
            cp_wait<1>();
            __syncthreads();                  // buf (tile&1) ready for all threads
            const float* hb = s_h + (tile & 1) * (TILE_JR * cCH);
            const int jr0 = tile * TILE_JR;
#pragma unroll
            for (int j = 0; j < TILE_JR; j++) {
                float2 hv = *reinterpret_cast<const float2*>(&hb[j * cCH + c2 * 2]);
                float a0 = p0[jr0 + j], a1 = p1[jr0 + j];
                float a2 = p2[jr0 + j], a3 = p3[jr0 + j];
                acc0.x += a0 * hv.x; acc0.y += a0 * hv.y;
                acc1.x += a1 * hv.x; acc1.y += a1 * hv.y;
                acc2.x += a2 * hv.x; acc2.y += a2 * hv.y;
                acc3.x += a3 * hv.x; acc3.y += a3 * hv.y;
            }
            __syncthreads();                  // everyone done reading buf before refill
            if (tile + 2 < N_JR_TILES) {
                const float* src = hbase + (tile + 2) * TILE_JR * cCH;
                unsigned int dst = s_h_addr + (tile & 1) * (TILE_JR * cCH * 4);
#pragma unroll
                for (int q = 0; q < 2; q++) {
                    int idx = t + 256 * q;
                    int r = idx >> 5, c4 = idx & 31;
                    cp_async16(dst + (r * cCH + c4 * 4) * 4, src + r * cCH + c4 * 4);
                }
            }
            cp_commit();                      // always one group per iter (may be empty)
        }

        const float inv0 = s_inv[rg * 4 + 0], inv1 = s_inv[rg * 4 + 1];
        const float inv2 = s_inv[rg * 4 + 2], inv3 = s_inv[rg * 4 + 3];
        acc0.x *= inv0; acc0.y *= inv0;
        acc1.x *= inv1; acc1.y *= inv1;
        acc2.x *= inv2; acc2.y *= inv2;
        acc3.x *= inv3; acc3.y *= inv3;
        if (LEAKY_OUT) {
            acc0.x = leaky(acc0.x); acc0.y = leaky(acc0.y);
            acc1.x = leaky(acc1.x); acc1.y = leaky(acc1.y);
            acc2.x = leaky(acc2.x); acc2.y = leaky(acc2.y);
            acc3.x = leaky(acc3.x); acc3.y = leaky(acc3.y);
        }
        *reinterpret_cast<float2*>(&g_atoms[(b * cN + i0 + rg * 4 + 0) * cCH + c2 * 2]) = acc0;
        *reinterpret_cast<float2*>(&g_atoms[(b * cN + i0 + rg * 4 + 1) * cCH + c2 * 2]) = acc1;
        *reinterpret_cast<float2*>(&g_atoms[(b * cN + i0 + rg * 4 + 2) * cCH + c2 * 2]) = acc2;
        *reinterpret_cast<float2*>(&g_atoms[(b * cN + i0 + rg * 4 + 3) * cCH + c2 * 2]) = acc3;
    }
}

// ---------------- 5) mean/max pooling over nodes ----------------
__global__ __launch_bounds__(512) void pool_kernel() {
    __shared__ float s_sum[4][cCH];
    __shared__ float s_max[4][cCH];
    const int b  = blockIdx.x;
    const int c  = threadIdx.x & 127;
    const int ch = threadIdx.x >> 7;   // 0..3, 64 nodes each
    float sum = 0.f, mx = -3.4e38f;
    for (int n = ch * 64; n < ch * 64 + 64; n++) {
        float v = g_atoms[(b * cN + n) * cCH + c];
        sum += v;
        mx = fmaxf(mx, v);
    }
    s_sum[ch][c] = sum;
    s_max[ch][c] = mx;
    __syncthreads();
    if (ch == 0) {
        sum = (s_sum[0][c] + s_sum[1][c]) + (s_sum[2][c] + s_sum[3][c]);
        mx = fmaxf(fmaxf(s_max[0][c], s_max[1][c]), fmaxf(s_max[2][c], s_max[3][c]));
        g_pool[b * 256 + c] = sum * (1.f / 256.f);
        g_pool[b * 256 + cCH + c] = mx;
    }
}

// ---------------- 6) final MLP (block per batch) ----------------
__global__ __launch_bounds__(256) void mlp_kernel(const float* __restrict__ x,
                                                  const float* __restrict__ We1, const float* __restrict__ be1,
                                                  const float* __restrict__ We2, const float* __restrict__ be2,
                                                  const float* __restrict__ We3, const float* __restrict__ be3,
                                                  float* __restrict__ out) {
    __shared__ float s_z[cXD + 256];
    __shared__ float s_h1[256];
    __shared__ float s_h2[32];
    const int b = blockIdx.x, t = threadIdx.x;
    for (int i = t; i < cXD; i += 256) s_z[i] = x[b * cXD + i];
    s_z[cXD + t] = g_pool[b * 256 + t];
    __syncthreads();
    {
        float a0 = 0.f, a1 = 0.f, a2 = 0.f, a3 = 0.f;
#pragma unroll 2
        for (int k = 0; k < cXD + 256; k += 4) {
            a0 += s_z[k + 0] * We1[(k + 0) * 256 + t];
            a1 += s_z[k + 1] * We1[(k + 1) * 256 + t];
            a2 += s_z[k + 2] * We1[(k + 2) * 256 + t];
            a3 += s_z[k + 3] * We1[(k + 3) * 256 + t];
        }
        float v = (a0 + a1) + (a2 + a3) + be1[t];
        s_h1[t] = leaky(v);
    }
    __syncthreads();
    if (t < 32) {
        float c0 = 0.f, c1 = 0.f, c2 = 0.f, c3 = 0.f;
        for (int k = 0; k < 256; k += 4) {
            c0 += s_h1[k + 0] * We2[(k + 0) * 32 + t];
            c1 += s_h1[k + 1] * We2[(k + 1) * 32 + t];
            c2 += s_h1[k + 2] * We2[(k + 2) * 32 + t];
            c3 += s_h1[k + 3] * We2[(k + 3) * 32 + t];
        }
        float u = (c0 + c1) + (c2 + c3) + be2[t];
        s_h2[t] = leaky(u);
    }
    __syncthreads();
    if (t < 32) {
        float p = s_h2[t] * We3[t];
#pragma unroll
        for (int o = 16; o; o >>= 1) p += __shfl_xor_sync(0xffffffffu, p, o);
        if (t == 0) out[b] = p + be3[0];
    }
}

// ---------------- launch ----------------
extern "C" void kernel_launch(void* const* d_in, const int* in_sizes, int n_in,
                              void* d_out, int out_size) {
    const float* x       = (const float*)d_in[0];
    const float* y_atoms = (const float*)d_in[1];
    const int*   y_bonds = (const int*)d_in[2];
    const float* W1 = (const float*)d_in[3];
    const float* b1 = (const float*)d_in[4];
    const float* a1 = (const float*)d_in[5];
    const float* W2 = (const float*)d_in[6];
    const float* b2 = (const float*)d_in[7];
    const float* a2 = (const float*)d_in[8];
    const float* W3 = (const float*)d_in[9];
    const float* b3 = (const float*)d_in[10];
    const float* a3 = (const float*)d_in[11];
    const float* We1 = (const float*)d_in[12];
    const float* be1 = (const float*)d_in[13];
    const float* We2 = (const float*)d_in[14];
    const float* be2 = (const float*)d_in[15];
    const float* We3 = (const float*)d_in[16];
    const float* be3 = (const float*)d_in[17];
    float* out = (float*)d_out;

    cudaFuncSetAttribute((const void*)attn_kernel<true>,
                         cudaFuncAttributeMaxDynamicSharedMemorySize, ATTN_SMEM);
    cudaFuncSetAttribute((const void*)attn_kernel<false>,
                         cudaFuncAttributeMaxDynamicSharedMemorySize, ATTN_SMEM);

    float* atoms_ptr = nullptr;
    cudaGetSymbolAddress((void**)&atoms_ptr, g_atoms);

    const dim3 gemm_grid(10, 128);

    pack_mask_kernel<<<(cB * cN * MASK_WORDS_PER_ROW + 255) / 256, 256>>>(y_bonds);

    // layer 1
    gemm_bias_kernel<cCIN><<<gemm_grid, 256>>>(y_atoms, W1, b1);
    src_dst_kernel<<<cB * cN, 160>>>(a1);
    attn_kernel<true><<<cB * 16, 256, ATTN_SMEM>>>();
    // layer 2
    gemm_bias_kernel<cCH><<<gemm_grid, 256>>>(atoms_ptr, W2, b2);
    src_dst_kernel<<<cB * cN, 160>>>(a2);
    attn_kernel<true><<<cB * 16, 256, ATTN_SMEM>>>();
    // layer 3
    gemm_bias_kernel<cCH><<<gemm_grid, 256>>>(atoms_ptr, W3, b3);
    src_dst_kernel<<<cB * cN, 160>>>(a3);
    attn_kernel<false><<<cB * 16, 256, ATTN_SMEM>>>();

    pool_kernel<<<cB, 512>>>();
    mlp_kernel<<<cB, 256>>>(x, We1, be1, We2, be2, We3, be3, out);
}

// round 4
// speedup vs baseline: 1.7473x; 1.4721x over previous
#include <cuda_runtime.h>
#include <cstdint>
#include <math.h>

// Problem constants
constexpr int cB   = 32;
constexpr int cN   = 256;
constexpr int cCIN = 64;
constexpr int cCH  = 128;   // C_H == C_OUT
constexpr int cR   = 5;
constexpr int cJR  = cN * cR;       // 1280
constexpr int cXD  = 1024;
constexpr float cNEG = -9e15f;

constexpr int MASK_WORDS_PER_ROW = cJR / 32;  // 40
constexpr int ATTN_TILE_I = 16;
constexpr int TILE_JR = 16;                    // H rows per smem stage
constexpr int N_JR_TILES = cJR / TILE_JR;      // 80
// smem floats: s_p 20480 + s_dst 1280 + s_src 80 + s_inv 16 + s_mask 640 + s_h 2*16*128
constexpr int ATTN_SMEM = (ATTN_TILE_I * cJR + cJR + ATTN_TILE_I * cR + ATTN_TILE_I
                           + ATTN_TILE_I * MASK_WORDS_PER_ROW
                           + 2 * TILE_JR * cCH) * 4;   // 106,368 B

// ---------------- device scratch (no cudaMalloc allowed) ----------------
__device__ float    g_h[cB * cN * cR * cCH];            // (b,n,r,c) == row-major (8192, 640)
__device__ float    g_atoms[cB * cN * cCH];             // layer activations (b,n,c)
__device__ float    g_src[cB * cN * cR];
__device__ float    g_dst[cB * cN * cR];
__device__ unsigned g_mask[cB * cN * MASK_WORDS_PER_ROW];
__device__ float    g_pool[cB * 2 * cCH];               // [mean(128) | max(128)] per batch

__device__ __forceinline__ float leaky(float v) { return v >= 0.f ? v : 0.2f * v; }

__device__ __forceinline__ void cp_async16(unsigned int smem_dst, const void* gsrc) {
    asm volatile("cp.async.cg.shared.global [%0], [%1], 16;\n" :: "r"(smem_dst), "l"(gsrc));
}
__device__ __forceinline__ void cp_commit() {
    asm volatile("cp.async.commit_group;\n");
}
template <int N>
__device__ __forceinline__ void cp_wait() {
    asm volatile("cp.async.wait_group %0;\n" :: "n"(N));
}

// packed f32x2 helpers (Blackwell FFMA2 path — PTX only)
__device__ __forceinline__ unsigned long long pack2(float lo, float hi) {
    unsigned long long r;
    asm("mov.b64 %0, {%1, %2};" : "=l"(r) : "f"(lo), "f"(hi));
    return r;
}
__device__ __forceinline__ void fma2(unsigned long long& d, unsigned long long a,
                                     unsigned long long b) {
    asm("fma.rn.f32x2 %0, %1, %2, %0;" : "+l"(d) : "l"(a), "l"(b));
}
__device__ __forceinline__ float2 unpack2(unsigned long long v) {
    float2 r;
    asm("mov.b64 {%0, %1}, %2;" : "=f"(r.x), "=f"(r.y) : "l"(v));
    return r;
}

// ---------------- 1) pack bond mask into bits ----------------
__global__ __launch_bounds__(256) void pack_mask_kernel(const int* __restrict__ bonds) {
    int w = blockIdx.x * blockDim.x + threadIdx.x;     // word index
    if (w >= cB * cN * MASK_WORDS_PER_ROW) return;
    const int4* p = reinterpret_cast<const int4*>(bonds) + w * 8;  // 32 ints
    unsigned m = 0;
#pragma unroll
    for (int q = 0; q < 8; q++) {
        int4 v = p[q];
        m |= (v.x == 1 ? 1u : 0u) << (q * 4 + 0);
        m |= (v.y == 1 ? 1u : 0u) << (q * 4 + 1);
        m |= (v.z == 1 ? 1u : 0u) << (q * 4 + 2);
        m |= (v.w == 1 ? 1u : 0u) << (q * 4 + 3);
    }
    g_mask[w] = m;
}

// ---------------- 2) h = A @ W + bias   (M=8192, N=640, K=64/128) ----------------
template <int K>
__global__ __launch_bounds__(256) void gemm_bias_kernel(const float* __restrict__ A,
                                                        const float* __restrict__ W,
                                                        const float* __restrict__ bias) {
    __shared__ float As[16][64];   // [k][m]
    __shared__ float Bs[16][64];   // [k][n]
    const int t  = threadIdx.x;
    const int tx = t & 15, ty = t >> 4;
    const int bm = blockIdx.y * 64, bn = blockIdx.x * 64;

    float acc[4][4];
#pragma unroll
    for (int i = 0; i < 4; i++)
#pragma unroll
        for (int j = 0; j < 4; j++) acc[i][j] = 0.f;

    const int arow = t >> 2, akq = t & 3;
    const int bkr = t >> 4, bn4 = t & 15;

    for (int bk = 0; bk < K; bk += 16) {
        float4 av = *reinterpret_cast<const float4*>(&A[(bm + arow) * K + bk + akq * 4]);
        As[akq * 4 + 0][arow] = av.x;
        As[akq * 4 + 1][arow] = av.y;
        As[akq * 4 + 2][arow] = av.z;
        As[akq * 4 + 3][arow] = av.w;
        *reinterpret_cast<float4*>(&Bs[bkr][bn4 * 4]) =
            *reinterpret_cast<const float4*>(&W[(bk + bkr) * 640 + bn + bn4 * 4]);
        __syncthreads();
#pragma unroll
        for (int k = 0; k < 16; k++) {
            float4 a  = *reinterpret_cast<float4*>(&As[k][ty * 4]);
            float4 bv = *reinterpret_cast<float4*>(&Bs[k][tx * 4]);
            acc[0][0] += a.x * bv.x; acc[0][1] += a.x * bv.y; acc[0][2] += a.x * bv.z; acc[0][3] += a.x * bv.w;
            acc[1][0] += a.y * bv.x; acc[1][1] += a.y * bv.y; acc[1][2] += a.y * bv.z; acc[1][3] += a.y * bv.w;
            acc[2][0] += a.z * bv.x; acc[2][1] += a.z * bv.y; acc[2][2] += a.z * bv.z; acc[2][3] += a.z * bv.w;
            acc[3][0] += a.w * bv.x; acc[3][1] += a.w * bv.y; acc[3][2] += a.w * bv.z; acc[3][3] += a.w * bv.w;
        }
        __syncthreads();
    }
    float4 bb = *reinterpret_cast<const float4*>(&bias[bn + tx * 4]);
#pragma unroll
    for (int i = 0; i < 4; i++) {
        float4 o;
        o.x = acc[i][0] + bb.x; o.y = acc[i][1] + bb.y;
        o.z = acc[i][2] + bb.z; o.w = acc[i][3] + bb.w;
        *reinterpret_cast<float4*>(&g_h[(bm + ty * 4 + i) * 640 + bn + tx * 4]) = o;
    }
}

// ---------------- 3) src/dst projections: (b,n,r) dots over c ----------------
__global__ __launch_bounds__(160) void src_dst_kernel(const float* __restrict__ a) {
    const int bn   = blockIdx.x;           // 0..8191
    const int r    = threadIdx.x >> 5;     // warp = relation
    const int lane = threadIdx.x & 31;
    const float* hrow = &g_h[(bn * cR + r) * cCH];
    float4 hv = *reinterpret_cast<const float4*>(&hrow[lane * 4]);
    float4 as = *reinterpret_cast<const float4*>(&a[r * (2 * cCH) + lane * 4]);
    float4 ad = *reinterpret_cast<const float4*>(&a[r * (2 * cCH) + cCH + lane * 4]);
    float s = hv.x * as.x + hv.y * as.y + hv.z * as.z + hv.w * as.w;
    float d = hv.x * ad.x + hv.y * ad.y + hv.z * ad.z + hv.w * ad.w;
#pragma unroll
    for (int o = 16; o; o >>= 1) {
        s += __shfl_xor_sync(0xffffffffu, s, o);
        d += __shfl_xor_sync(0xffffffffu, d, o);
    }
    if (lane == 0) {
        g_src[bn * cR + r] = s;
        g_dst[bn * cR + r] = d;
    }
}

// ---------------- 4) fused masked softmax + aggregation ----------------
// Block: (b, i-tile of 16 rows), 256 threads.
// Phase 2: cp.async double-buffered H stream + packed fma.rn.f32x2 register tile
// (2 rows x 4 cols per thread).
template <bool LEAKY_OUT>
__global__ __launch_bounds__(256) void attn_kernel() {
    extern __shared__ float sm[];
    float*    s_p    = sm;                              // 16*1280 (unnormalized exp)
    float*    s_dst  = s_p + ATTN_TILE_I * cJR;         // 1280
    float*    s_src  = s_dst + cJR;                     // 80
    float*    s_inv  = s_src + ATTN_TILE_I * cR;        // 16
    unsigned* s_mask = reinterpret_cast<unsigned*>(s_inv + ATTN_TILE_I); // 640 words
    float*    s_h    = reinterpret_cast<float*>(s_mask + ATTN_TILE_I * MASK_WORDS_PER_ROW);
                                                        // 2 * 16 * 128 (16B aligned)

    const int b  = blockIdx.x >> 4;
    const int i0 = (blockIdx.x & 15) * ATTN_TILE_I;
    const int t  = threadIdx.x;

    const float* hbase = &g_h[(size_t)b * cJR * cCH];
    const unsigned int s_h_addr = (unsigned int)__cvta_generic_to_shared(s_h);

    // issue the first two H tiles immediately (latency hidden under phase 1)
#pragma unroll
    for (int tile = 0; tile < 2; tile++) {
        const float* src = hbase + tile * TILE_JR * cCH;
        unsigned int dst = s_h_addr + tile * (TILE_JR * cCH * 4);
#pragma unroll
        for (int q = 0; q < 2; q++) {
            int idx = t + 256 * q;
            int r = idx >> 5, c4 = idx & 31;
            cp_async16(dst + (r * cCH + c4 * 4) * 4, src + r * cCH + c4 * 4);
        }
        cp_commit();
    }

    for (int idx = t; idx < cJR; idx += 256) s_dst[idx] = g_dst[b * cJR + idx];
    if (t < ATTN_TILE_I * cR) s_src[t] = g_src[(b * cN + i0) * cR + t];
    for (int idx = t; idx < ATTN_TILE_I * MASK_WORDS_PER_ROW; idx += 256)
        s_mask[idx] = g_mask[(b * cN + i0) * MASK_WORDS_PER_ROW + idx];
    __syncthreads();

    // ---- phase 1: masked leaky logits -> max -> exp -> sum (16 threads / row)
    {
        const int row = t >> 4, l16 = t & 15;
        float* prow = s_p + row * cJR;
        const float* srcr = s_src + row * cR;
        const unsigned* mrow = s_mask + row * MASK_WORDS_PER_ROW;

        float mx = cNEG;
        for (int e = l16; e < cJR; e += 16) {
            int r = e % 5;
            float v = leaky(srcr[r] + s_dst[e]);
            unsigned bit = (mrow[e >> 5] >> (e & 31)) & 1u;
            v = bit ? v : cNEG;
            prow[e] = v;
            mx = fmaxf(mx, v);
        }
#pragma unroll
        for (int o = 8; o; o >>= 1) mx = fmaxf(mx, __shfl_xor_sync(0xffffffffu, mx, o));

        float sum = 0.f;
        for (int e = l16; e < cJR; e += 16) {
            float ev = __expf(prow[e] - mx);
            prow[e] = ev;
            sum += ev;
        }
#pragma unroll
        for (int o = 8; o; o >>= 1) sum += __shfl_xor_sync(0xffffffffu, sum, o);
        if (l16 == 0) s_inv[row] = 1.f / sum;
    }
    __syncthreads();

    // ---- phase 2: out[16][128] = P[16][1280] @ H[1280][128], H staged via cp.async
    // 2 rows x 4 cols per thread: 1 LDS.128 (hv) + 2 bcast LDS (p) + 2 pack + 4 FFMA2 per j.
    {
        const int c4 = t & 31;                // cols c4*4 .. c4*4+3
        const int rg = t >> 5;                // row groups: rows rg*2, rg*2+1
        const int r0 = rg * 2, r1 = rg * 2 + 1;
        const float* p0 = s_p + r0 * cJR;
        const float* p1 = s_p + r1 * cJR;

        unsigned long long acc00 = 0, acc01 = 0, acc10 = 0, acc11 = 0;  // f32x2 {0,0}

        for (int tile = 0; tile < N_JR_TILES; tile++) {
            cp_wait<1>();
            __syncthreads();                  // buf (tile&1) ready for all threads
            const float* hb = s_h + (tile & 1) * (TILE_JR * cCH) + c4 * 4;
            const float* q0 = p0 + tile * TILE_JR;
            const float* q1 = p1 + tile * TILE_JR;
#pragma unroll
            for (int j = 0; j < TILE_JR; j++) {
                ulonglong2 hv = *reinterpret_cast<const ulonglong2*>(&hb[j * cCH]);
                unsigned long long pa0 = pack2(q0[j], q0[j]);
                unsigned long long pa1 = pack2(q1[j], q1[j]);
                fma2(acc00, pa0, hv.x);
                fma2(acc01, pa0, hv.y);
                fma2(acc10, pa1, hv.x);
                fma2(acc11, pa1, hv.y);
            }
            __syncthreads();                  // everyone done reading buf before refill
            if (tile + 2 < N_JR_TILES) {
                const float* src = hbase + (tile + 2) * TILE_JR * cCH;
                unsigned int dst = s_h_addr + (tile & 1) * (TILE_JR * cCH * 4);
#pragma unroll
                for (int q = 0; q < 2; q++) {
                    int idx = t + 256 * q;
                    int r = idx >> 5, cc = idx & 31;
                    cp_async16(dst + (r * cCH + cc * 4) * 4, src + r * cCH + cc * 4);
                }
            }
            cp_commit();                      // always one group per iter (may be empty)
        }

        const float inv0 = s_inv[r0], inv1 = s_inv[r1];
        float2 v00 = unpack2(acc00), v01 = unpack2(acc01);
        float2 v10 = unpack2(acc10), v11 = unpack2(acc11);
        float4 o0 = {v00.x * inv0, v00.y * inv0, v01.x * inv0, v01.y * inv0};
        float4 o1 = {v10.x * inv1, v10.y * inv1, v11.x * inv1, v11.y * inv1};
        if (LEAKY_OUT) {
            o0.x = leaky(o0.x); o0.y = leaky(o0.y); o0.z = leaky(o0.z); o0.w = leaky(o0.w);
            o1.x = leaky(o1.x); o1.y = leaky(o1.y); o1.z = leaky(o1.z); o1.w = leaky(o1.w);
        }
        *reinterpret_cast<float4*>(&g_atoms[(b * cN + i0 + r0) * cCH + c4 * 4]) = o0;
        *reinterpret_cast<float4*>(&g_atoms[(b * cN + i0 + r1) * cCH + c4 * 4]) = o1;
    }
}

// ---------------- 5) mean/max pooling over nodes ----------------
__global__ __launch_bounds__(512) void pool_kernel() {
    __shared__ float s_sum[4][cCH];
    __shared__ float s_max[4][cCH];
    const int b  = blockIdx.x;
    const int c  = threadIdx.x & 127;
    const int ch = threadIdx.x >> 7;   // 0..3, 64 nodes each
    float sum = 0.f, mx = -3.4e38f;
    for (int n = ch * 64; n < ch * 64 + 64; n++) {
        float v = g_atoms[(b * cN + n) * cCH + c];
        sum += v;
        mx = fmaxf(mx, v);
    }
    s_sum[ch][c] = sum;
    s_max[ch][c] = mx;
    __syncthreads();
    if (ch == 0) {
        sum = (s_sum[0][c] + s_sum[1][c]) + (s_sum[2][c] + s_sum[3][c]);
        mx = fmaxf(fmaxf(s_max[0][c], s_max[1][c]), fmaxf(s_max[2][c], s_max[3][c]));
        g_pool[b * 256 + c] = sum * (1.f / 256.f);
        g_pool[b * 256 + cCH + c] = mx;
    }
}

// ---------------- 6) final MLP (block per batch) ----------------
__global__ __launch_bounds__(256) void mlp_kernel(const float* __restrict__ x,
                                                  const float* __restrict__ We1, const float* __restrict__ be1,
                                                  const float* __restrict__ We2, const float* __restrict__ be2,
                                                  const float* __restrict__ We3, const float* __restrict__ be3,
                                                  float* __restrict__ out) {
    __shared__ float s_z[cXD + 256];
    __shared__ float s_h1[256];
    __shared__ float s_h2[32];
    const int b = blockIdx.x, t = threadIdx.x;
    for (int i = t; i < cXD; i += 256) s_z[i] = x[b * cXD + i];
    s_z[cXD + t] = g_pool[b * 256 + t];
    __syncthreads();
    {
        float a0 = 0.f, a1 = 0.f, a2 = 0.f, a3 = 0.f;
#pragma unroll 2
        for (int k = 0; k < cXD + 256; k += 4) {
            a0 += s_z[k + 0] * We1[(k + 0) * 256 + t];
            a1 += s_z[k + 1] * We1[(k + 1) * 256 + t];
            a2 += s_z[k + 2] * We1[(k + 2) * 256 + t];
            a3 += s_z[k + 3] * We1[(k + 3) * 256 + t];
        }
        float v = (a0 + a1) + (a2 + a3) + be1[t];
        s_h1[t] = leaky(v);
    }
    __syncthreads();
    if (t < 32) {
        float c0 = 0.f, c1 = 0.f, c2 = 0.f, c3 = 0.f;
        for (int k = 0; k < 256; k += 4) {
            c0 += s_h1[k + 0] * We2[(k + 0) * 32 + t];
            c1 += s_h1[k + 1] * We2[(k + 1) * 32 + t];
            c2 += s_h1[k + 2] * We2[(k + 2) * 32 + t];
            c3 += s_h1[k + 3] * We2[(k + 3) * 32 + t];
        }
        float u = (c0 + c1) + (c2 + c3) + be2[t];
        s_h2[t] = leaky(u);
    }
    __syncthreads();
    if (t < 32) {
        float p = s_h2[t] * We3[t];
#pragma unroll
        for (int o = 16; o; o >>= 1) p += __shfl_xor_sync(0xffffffffu, p, o);
        if (t == 0) out[b] = p + be3[0];
    }
}

// ---------------- launch ----------------
extern "C" void kernel_launch(void* const* d_in, const int* in_sizes, int n_in,
                              void* d_out, int out_size) {
    const float* x       = (const float*)d_in[0];
    const float* y_atoms = (const float*)d_in[1];
    const int*   y_bonds = (const int*)d_in[2];
    const float* W1 = (const float*)d_in[3];
    const float* b1 = (const float*)d_in[4];
    const float* a1 = (const float*)d_in[5];
    const float* W2 = (const float*)d_in[6];
    const float* b2 = (const float*)d_in[7];
    const float* a2 = (const float*)d_in[8];
    const float* W3 = (const float*)d_in[9];
    const float* b3 = (const float*)d_in[10];
    const float* a3 = (const float*)d_in[11];
    const float* We1 = (const float*)d_in[12];
    const float* be1 = (const float*)d_in[13];
    const float* We2 = (const float*)d_in[14];
    const float* be2 = (const float*)d_in[15];
    const float* We3 = (const float*)d_in[16];
    const float* be3 = (const float*)d_in[17];
    float* out = (float*)d_out;

    cudaFuncSetAttribute((const void*)attn_kernel<true>,
                         cudaFuncAttributeMaxDynamicSharedMemorySize, ATTN_SMEM);
    cudaFuncSetAttribute((const void*)attn_kernel<false>,
                         cudaFuncAttributeMaxDynamicSharedMemorySize, ATTN_SMEM);

    float* atoms_ptr = nullptr;
    cudaGetSymbolAddress((void**)&atoms_ptr, g_atoms);

    const dim3 gemm_grid(10, 128);

    pack_mask_kernel<<<(cB * cN * MASK_WORDS_PER_ROW + 255) / 256, 256>>>(y_bonds);

    // layer 1
    gemm_bias_kernel<cCIN><<<gemm_grid, 256>>>(y_atoms, W1, b1);
    src_dst_kernel<<<cB * cN, 160>>>(a1);
    attn_kernel<true><<<cB * 16, 256, ATTN_SMEM>>>();
    // layer 2
    gemm_bias_kernel<cCH><<<gemm_grid, 256>>>(atoms_ptr, W2, b2);
    src_dst_kernel<<<cB * cN, 160>>>(a2);
    attn_kernel<true><<<cB * 16, 256, ATTN_SMEM>>>();
    // layer 3
    gemm_bias_kernel<cCH><<<gemm_grid, 256>>>(atoms_ptr, W3, b3);
    src_dst_kernel<<<cB * cN, 160>>>(a3);
    attn_kernel<false><<<cB * 16, 256, ATTN_SMEM>>>();

    pool_kernel<<<cB, 512>>>();
    mlp_kernel<<<cB, 256>>>(x, We1, be1, We2, be2, We3, be3, out);
}

// round 5
// speedup vs baseline: 2.0527x; 1.1748x over previous
#include <cuda_runtime.h>
#include <cstdint>
#include <math.h>

// Problem constants
constexpr int cB   = 32;
constexpr int cN   = 256;
constexpr int cCIN = 64;
constexpr int cCH  = 128;   // C_H == C_OUT
constexpr int cR   = 5;
constexpr int cJR  = cN * cR;       // 1280
constexpr int cXD  = 1024;
constexpr float cNEG = -9e15f;

constexpr int MASK_WORDS_PER_ROW = cJR / 32;  // 40
constexpr int ATTN_TILE_I = 32;                // i-rows per block
constexpr int N_ITILES = cN / ATTN_TILE_I;     // 8
constexpr int P_STRIDE = 36;                   // padded row stride of transposed s_p (floats)
constexpr int TILE_JR = 16;                    // H rows per smem stage
constexpr int N_JR_TILES = cJR / TILE_JR;      // 80
// smem floats: s_p 1280*36 + s_dst 1280 + s_src 160 + s_inv 32 + s_mask 1280 + s_h 2*16*128
constexpr int ATTN_SMEM = (cJR * P_STRIDE + cJR + ATTN_TILE_I * cR + ATTN_TILE_I
                           + ATTN_TILE_I * MASK_WORDS_PER_ROW
                           + 2 * TILE_JR * cCH) * 4;   // 211,712 B

// ---------------- device scratch (no cudaMalloc allowed) ----------------
__device__ float    g_h[cB * cN * cR * cCH];            // (b,n,r,c) == row-major (8192, 640)
__device__ float    g_atoms[cB * cN * cCH];             // layer activations (b,n,c)
__device__ float    g_src[cB * cN * cR];
__device__ float    g_dst[cB * cN * cR];
__device__ unsigned g_mask[cB * cN * MASK_WORDS_PER_ROW];
__device__ float    g_pool[cB * 2 * cCH];               // [mean(128) | max(128)] per batch

__device__ __forceinline__ float leaky(float v) { return v >= 0.f ? v : 0.2f * v; }

__device__ __forceinline__ void cp_async16(unsigned int smem_dst, const void* gsrc) {
    asm volatile("cp.async.cg.shared.global [%0], [%1], 16;\n" :: "r"(smem_dst), "l"(gsrc));
}
__device__ __forceinline__ void cp_commit() {
    asm volatile("cp.async.commit_group;\n");
}
template <int N>
__device__ __forceinline__ void cp_wait() {
    asm volatile("cp.async.wait_group %0;\n" :: "n"(N));
}

// packed f32x2 helpers (Blackwell FFMA2 path — PTX only)
__device__ __forceinline__ unsigned long long pack2(float lo, float hi) {
    unsigned long long r;
    asm("mov.b64 %0, {%1, %2};" : "=l"(r) : "f"(lo), "f"(hi));
    return r;
}
__device__ __forceinline__ void fma2(unsigned long long& d, unsigned long long a,
                                     unsigned long long b) {
    asm("fma.rn.f32x2 %0, %1, %2, %0;" : "+l"(d) : "l"(a), "l"(b));
}
__device__ __forceinline__ float2 unpack2(unsigned long long v) {
    float2 r;
    asm("mov.b64 {%0, %1}, %2;" : "=f"(r.x), "=f"(r.y) : "l"(v));
    return r;
}

// ---------------- 1) pack bond mask into bits ----------------
__global__ __launch_bounds__(256) void pack_mask_kernel(const int* __restrict__ bonds) {
    int w = blockIdx.x * blockDim.x + threadIdx.x;     // word index
    if (w >= cB * cN * MASK_WORDS_PER_ROW) return;
    const int4* p = reinterpret_cast<const int4*>(bonds) + w * 8;  // 32 ints
    unsigned m = 0;
#pragma unroll
    for (int q = 0; q < 8; q++) {
        int4 v = p[q];
        m |= (v.x == 1 ? 1u : 0u) << (q * 4 + 0);
        m |= (v.y == 1 ? 1u : 0u) << (q * 4 + 1);
        m |= (v.z == 1 ? 1u : 0u) << (q * 4 + 2);
        m |= (v.w == 1 ? 1u : 0u) << (q * 4 + 3);
    }
    g_mask[w] = m;
}

// ---------------- 2) h = A @ W + bias   (M=8192, N=640, K=64/128) ----------------
template <int K>
__global__ __launch_bounds__(256) void gemm_bias_kernel(const float* __restrict__ A,
                                                        const float* __restrict__ W,
                                                        const float* __restrict__ bias) {
    __shared__ float As[16][64];   // [k][m]
    __shared__ float Bs[16][64];   // [k][n]
    const int t  = threadIdx.x;
    const int tx = t & 15, ty = t >> 4;
    const int bm = blockIdx.y * 64, bn = blockIdx.x * 64;

    unsigned long long accp[4][2];
#pragma unroll
    for (int i = 0; i < 4; i++) { accp[i][0] = 0ull; accp[i][1] = 0ull; }

    const int arow = t >> 2, akq = t & 3;
    const int bkr = t >> 4, bn4 = t & 15;

    for (int bk = 0; bk < K; bk += 16) {
        float4 av = *reinterpret_cast<const float4*>(&A[(bm + arow) * K + bk + akq * 4]);
        As[akq * 4 + 0][arow] = av.x;
        As[akq * 4 + 1][arow] = av.y;
        As[akq * 4 + 2][arow] = av.z;
        As[akq * 4 + 3][arow] = av.w;
        *reinterpret_cast<float4*>(&Bs[bkr][bn4 * 4]) =
            *reinterpret_cast<const float4*>(&W[(bk + bkr) * 640 + bn + bn4 * 4]);
        __syncthreads();
#pragma unroll
        for (int k = 0; k < 16; k++) {
            float4 a  = *reinterpret_cast<float4*>(&As[k][ty * 4]);
            float4 bv = *reinterpret_cast<float4*>(&Bs[k][tx * 4]);
            unsigned long long b01 = pack2(bv.x, bv.y), b23 = pack2(bv.z, bv.w);
            unsigned long long pa;
            pa = pack2(a.x, a.x); fma2(accp[0][0], pa, b01); fma2(accp[0][1], pa, b23);
            pa = pack2(a.y, a.y); fma2(accp[1][0], pa, b01); fma2(accp[1][1], pa, b23);
            pa = pack2(a.z, a.z); fma2(accp[2][0], pa, b01); fma2(accp[2][1], pa, b23);
            pa = pack2(a.w, a.w); fma2(accp[3][0], pa, b01); fma2(accp[3][1], pa, b23);
        }
        __syncthreads();
    }
    float4 bb = *reinterpret_cast<const float4*>(&bias[bn + tx * 4]);
#pragma unroll
    for (int i = 0; i < 4; i++) {
        float2 lo = unpack2(accp[i][0]), hi = unpack2(accp[i][1]);
        float4 o;
        o.x = lo.x + bb.x; o.y = lo.y + bb.y;
        o.z = hi.x + bb.z; o.w = hi.y + bb.w;
        *reinterpret_cast<float4*>(&g_h[(bm + ty * 4 + i) * 640 + bn + tx * 4]) = o;
    }
}

// ---------------- 3) src/dst projections: (b,n,r) dots over c ----------------
__global__ __launch_bounds__(160) void src_dst_kernel(const float* __restrict__ a) {
    const int bn   = blockIdx.x;           // 0..8191
    const int r    = threadIdx.x >> 5;     // warp = relation
    const int lane = threadIdx.x & 31;
    const float* hrow = &g_h[(bn * cR + r) * cCH];
    float4 hv = *reinterpret_cast<const float4*>(&hrow[lane * 4]);
    float4 as = *reinterpret_cast<const float4*>(&a[r * (2 * cCH) + lane * 4]);
    float4 ad = *reinterpret_cast<const float4*>(&a[r * (2 * cCH) + cCH + lane * 4]);
    float s = hv.x * as.x + hv.y * as.y + hv.z * as.z + hv.w * as.w;
    float d = hv.x * ad.x + hv.y * ad.y + hv.z * ad.z + hv.w * ad.w;
#pragma unroll
    for (int o = 16; o; o >>= 1) {
        s += __shfl_xor_sync(0xffffffffu, s, o);
        d += __shfl_xor_sync(0xffffffffu, d, o);
    }
    if (lane == 0) {
        g_src[bn * cR + r] = s;
        g_dst[bn * cR + r] = d;
    }
}

// ---------------- 4) fused masked softmax + aggregation ----------------
// Block: (b, i-tile of 32 rows), 256 threads.
// s_p stored TRANSPOSED: s_p[jr * P_STRIDE + row]. Phase 2: per thread 4 rows x 4 cols,
// p via one broadcast LDS.128 per warp per j, H streamed via cp.async double buffer,
// accumulation in packed fma.rn.f32x2.
template <bool LEAKY_OUT>
__global__ __launch_bounds__(256) void attn_kernel() {
    extern __shared__ float sm[];
    float*    s_p    = sm;                               // [1280][36] transposed
    float*    s_dst  = s_p + cJR * P_STRIDE;             // 1280
    float*    s_src  = s_dst + cJR;                      // 32*5
    float*    s_inv  = s_src + ATTN_TILE_I * cR;         // 32
    unsigned* s_mask = reinterpret_cast<unsigned*>(s_inv + ATTN_TILE_I); // 32*40 words
    float*    s_h    = reinterpret_cast<float*>(s_mask + ATTN_TILE_I * MASK_WORDS_PER_ROW);
                                                         // 2 * 16 * 128 (16B aligned)

    const int b  = blockIdx.x >> 3;
    const int i0 = (blockIdx.x & 7) * ATTN_TILE_I;
    const int t  = threadIdx.x;

    const float* hbase = &g_h[(size_t)b * cJR * cCH];
    const unsigned int s_h_addr = (unsigned int)__cvta_generic_to_shared(s_h);

    // issue the first two H tiles immediately (latency hidden under phase 1)
#pragma unroll
    for (int tile = 0; tile < 2; tile++) {
        const float* src = hbase + tile * TILE_JR * cCH;
        unsigned int dst = s_h_addr + tile * (TILE_JR * cCH * 4);
#pragma unroll
        for (int q = 0; q < 2; q++) {
            int idx = t + 256 * q;
            int r = idx >> 5, c4 = idx & 31;
            cp_async16(dst + (r * cCH + c4 * 4) * 4, src + r * cCH + c4 * 4);
        }
        cp_commit();
    }

    for (int idx = t; idx < cJR; idx += 256) s_dst[idx] = g_dst[b * cJR + idx];
    if (t < ATTN_TILE_I * cR) s_src[t] = g_src[(b * cN + i0) * cR + t];
    for (int idx = t; idx < ATTN_TILE_I * MASK_WORDS_PER_ROW; idx += 256)
        s_mask[idx] = g_mask[(b * cN + i0) * MASK_WORDS_PER_ROW + idx];
    __syncthreads();

    // ---- phase 1: masked leaky logits -> max -> exp -> sum (8 threads / row)
    {
        const int row = t >> 3, l8 = t & 7;
        const float* srcr = s_src + row * cR;
        const unsigned* mrow = s_mask + row * MASK_WORDS_PER_ROW;

        float mx = cNEG;
        for (int e = l8; e < cJR; e += 8) {
            int r = e % 5;
            float v = leaky(srcr[r] + s_dst[e]);
            unsigned bit = (mrow[e >> 5] >> (e & 31)) & 1u;
            v = bit ? v : cNEG;
            s_p[e * P_STRIDE + row] = v;
            mx = fmaxf(mx, v);
        }
#pragma unroll
        for (int o = 4; o; o >>= 1) mx = fmaxf(mx, __shfl_xor_sync(0xffffffffu, mx, o));

        float sum = 0.f;
        for (int e = l8; e < cJR; e += 8) {
            float ev = __expf(s_p[e * P_STRIDE + row] - mx);
            s_p[e * P_STRIDE + row] = ev;
            sum += ev;
        }
#pragma unroll
        for (int o = 4; o; o >>= 1) sum += __shfl_xor_sync(0xffffffffu, sum, o);
        if (l8 == 0) s_inv[row] = 1.f / sum;
    }
    __syncthreads();

    // ---- phase 2: out[32][128] = P[32][1280]^T-stored @ H[1280][128]
    // thread: warp rg=t>>5 handles rows rg*4..+3, lane c4=t&31 handles cols c4*4..+3.
    {
        const int c4 = t & 31;
        const int rg = t >> 5;
        unsigned long long acc[4][2];
#pragma unroll
        for (int i = 0; i < 4; i++) { acc[i][0] = 0ull; acc[i][1] = 0ull; }

        const float* pp_base = s_p + rg * 4;

        for (int tile = 0; tile < N_JR_TILES; tile++) {
            cp_wait<1>();
            __syncthreads();                  // buf (tile&1) ready for all threads
            const float* hh = s_h + (tile & 1) * (TILE_JR * cCH) + c4 * 4;
            const float* pp = pp_base + tile * TILE_JR * P_STRIDE;
#pragma unroll
            for (int j = 0; j < TILE_JR; j++) {
                float4 p4 = *reinterpret_cast<const float4*>(pp);  // warp-uniform broadcast
                ulonglong2 hv = *reinterpret_cast<const ulonglong2*>(hh);
                unsigned long long pa;
                pa = pack2(p4.x, p4.x); fma2(acc[0][0], pa, hv.x); fma2(acc[0][1], pa, hv.y);
                pa = pack2(p4.y, p4.y); fma2(acc[1][0], pa, hv.x); fma2(acc[1][1], pa, hv.y);
                pa = pack2(p4.z, p4.z); fma2(acc[2][0], pa, hv.x); fma2(acc[2][1], pa, hv.y);
                pa = pack2(p4.w, p4.w); fma2(acc[3][0], pa, hv.x); fma2(acc[3][1], pa, hv.y);
                pp += P_STRIDE;
                hh += cCH;
            }
            __syncthreads();                  // everyone done reading buf before refill
            if (tile + 2 < N_JR_TILES) {
                const float* src = hbase + (tile + 2) * TILE_JR * cCH;
                unsigned int dst = s_h_addr + (tile & 1) * (TILE_JR * cCH * 4);
#pragma unroll
                for (int q = 0; q < 2; q++) {
                    int idx = t + 256 * q;
                    int r = idx >> 5, cc = idx & 31;
                    cp_async16(dst + (r * cCH + cc * 4) * 4, src + r * cCH + cc * 4);
                }
            }
            cp_commit();                      // always one group per iter (may be empty)
        }

#pragma unroll
        for (int i = 0; i < 4; i++) {
            const int row = rg * 4 + i;
            const float inv = s_inv[row];
            float2 lo = unpack2(acc[i][0]), hi = unpack2(acc[i][1]);
            float4 o = {lo.x * inv, lo.y * inv, hi.x * inv, hi.y * inv};
            if (LEAKY_OUT) {
                o.x = leaky(o.x); o.y = leaky(o.y); o.z = leaky(o.z); o.w = leaky(o.w);
            }
            *reinterpret_cast<float4*>(&g_atoms[(b * cN + i0 + row) * cCH + c4 * 4]) = o;
        }
    }
}

// ---------------- 5) mean/max pooling over nodes ----------------
__global__ __launch_bounds__(512) void pool_kernel() {
    __shared__ float s_sum[4][cCH];
    __shared__ float s_max[4][cCH];
    const int b  = blockIdx.x;
    const int c  = threadIdx.x & 127;
    const int ch = threadIdx.x >> 7;   // 0..3, 64 nodes each
    float sum = 0.f, mx = -3.4e38f;
    for (int n = ch * 64; n < ch * 64 + 64; n++) {
        float v = g_atoms[(b * cN + n) * cCH + c];
        sum += v;
        mx = fmaxf(mx, v);
    }
    s_sum[ch][c] = sum;
    s_max[ch][c] = mx;
    __syncthreads();
    if (ch == 0) {
        sum = (s_sum[0][c] + s_sum[1][c]) + (s_sum[2][c] + s_sum[3][c]);
        mx = fmaxf(fmaxf(s_max[0][c], s_max[1][c]), fmaxf(s_max[2][c], s_max[3][c]));
        g_pool[b * 256 + c] = sum * (1.f / 256.f);
        g_pool[b * 256 + cCH + c] = mx;
    }
}

// ---------------- 6) final MLP (block per batch) ----------------
__global__ __launch_bounds__(256) void mlp_kernel(const float* __restrict__ x,
                                                  const float* __restrict__ We1, const float* __restrict__ be1,
                                                  const float* __restrict__ We2, const float* __restrict__ be2,
                                                  const float* __restrict__ We3, const float* __restrict__ be3,
                                                  float* __restrict__ out) {
    __shared__ float s_z[cXD + 256];
    __shared__ float s_h1[256];
    __shared__ float s_h2[32];
    const int b = blockIdx.x, t = threadIdx.x;
    for (int i = t; i < cXD; i += 256) s_z[i] = x[b * cXD + i];
    s_z[cXD + t] = g_pool[b * 256 + t];
    __syncthreads();
    {
        float a0 = 0.f, a1 = 0.f, a2 = 0.f, a3 = 0.f;
#pragma unroll 2
        for (int k = 0; k < cXD + 256; k += 4) {
            a0 += s_z[k + 0] * We1[(k + 0) * 256 + t];
            a1 += s_z[k + 1] * We1[(k + 1) * 256 + t];
            a2 += s_z[k + 2] * We1[(k + 2) * 256 + t];
            a3 += s_z[k + 3] * We1[(k + 3) * 256 + t];
        }
        float v = (a0 + a1) + (a2 + a3) + be1[t];
        s_h1[t] = leaky(v);
    }
    __syncthreads();
    if (t < 32) {
        float c0 = 0.f, c1 = 0.f, c2 = 0.f, c3 = 0.f;
        for (int k = 0; k < 256; k += 4) {
            c0 += s_h1[k + 0] * We2[(k + 0) * 32 + t];
            c1 += s_h1[k + 1] * We2[(k + 1) * 32 + t];
            c2 += s_h1[k + 2] * We2[(k + 2) * 32 + t];
            c3 += s_h1[k + 3] * We2[(k + 3) * 32 + t];
        }
        float u = (c0 + c1) + (c2 + c3) + be2[t];
        s_h2[t] = leaky(u);
    }
    __syncthreads();
    if (t < 32) {
        float p = s_h2[t] * We3[t];
#pragma unroll
        for (int o = 16; o; o >>= 1) p += __shfl_xor_sync(0xffffffffu, p, o);
        if (t == 0) out[b] = p + be3[0];
    }
}

// ---------------- launch ----------------
extern "C" void kernel_launch(void* const* d_in, const int* in_sizes, int n_in,
                              void* d_out, int out_size) {
    const float* x       = (const float*)d_in[0];
    const float* y_atoms = (const float*)d_in[1];
    const int*   y_bonds = (const int*)d_in[2];
    const float* W1 = (const float*)d_in[3];
    const float* b1 = (const float*)d_in[4];
    const float* a1 = (const float*)d_in[5];
    const float* W2 = (const float*)d_in[6];
    const float* b2 = (const float*)d_in[7];
    const float* a2 = (const float*)d_in[8];
    const float* W3 = (const float*)d_in[9];
    const float* b3 = (const float*)d_in[10];
    const float* a3 = (const float*)d_in[11];
    const float* We1 = (const float*)d_in[12];
    const float* be1 = (const float*)d_in[13];
    const float* We2 = (const float*)d_in[14];
    const float* be2 = (const float*)d_in[15];
    const float* We3 = (const float*)d_in[16];
    const float* be3 = (const float*)d_in[17];
    float* out = (float*)d_out;

    cudaFuncSetAttribute((const void*)attn_kernel<true>,
                         cudaFuncAttributeMaxDynamicSharedMemorySize, ATTN_SMEM);
    cudaFuncSetAttribute((const void*)attn_kernel<false>,
                         cudaFuncAttributeMaxDynamicSharedMemorySize, ATTN_SMEM);

    float* atoms_ptr = nullptr;
    cudaGetSymbolAddress((void**)&atoms_ptr, g_atoms);

    const dim3 gemm_grid(10, 128);
    const int attn_grid = cB * N_ITILES;   // 256

    pack_mask_kernel<<<(cB * cN * MASK_WORDS_PER_ROW + 255) / 256, 256>>>(y_bonds);

    // layer 1
    gemm_bias_kernel<cCIN><<<gemm_grid, 256>>>(y_atoms, W1, b1);
    src_dst_kernel<<<cB * cN, 160>>>(a1);
    attn_kernel<true><<<attn_grid, 256, ATTN_SMEM>>>();
    // layer 2
    gemm_bias_kernel<cCH><<<gemm_grid, 256>>>(atoms_ptr, W2, b2);
    src_dst_kernel<<<cB * cN, 160>>>(a2);
    attn_kernel<true><<<attn_grid, 256, ATTN_SMEM>>>();
    // layer 3
    gemm_bias_kernel<cCH><<<gemm_grid, 256>>>(atoms_ptr, W3, b3);
    src_dst_kernel<<<cB * cN, 160>>>(a3);
    attn_kernel<false><<<attn_grid, 256, ATTN_SMEM>>>();

    pool_kernel<<<cB, 512>>>();
    mlp_kernel<<<cB, 256>>>(x, We1, be1, We2, be2, We3, be3, out);
}